// round 9
// baseline (speedup 1.0000x reference)
#include <cuda_runtime.h>
#include <cstdint>

#define Bb 32
#define Dd 20
#define Ll 4096
#define Kk 1000
#define Nn (Bb*Ll)
#define NDLs (Bb*Dd*Ll)
#define NUNITS (Nn/16)          // 8192 m16 tiles
#define NBLK 148
#define WPB 16
#define NTHR (WPB*32)           // 512
#define NWARPS (NBLK*WPB)       // 2368
#define HWORDS (1024*24)
#define SMEM_BYTES (2*HWORDS*4) // 196608 B

__device__ int   g_work;
__device__ float g_kl;
__device__ int   g_hist[Kk];
__device__ int   g_done;

__device__ __forceinline__ uint32_t tf32h(float v){
  uint32_t r; asm("cvt.rna.tf32.f32 %0, %1;" : "=r"(r) : "f"(v)); return r;
}
__device__ __forceinline__ void mma_tf32(float* d, const uint32_t* a, const uint32_t* b, const float* c){
  asm volatile("mma.sync.aligned.m16n8k8.row.col.f32.tf32.tf32.f32 "
    "{%0,%1,%2,%3},{%4,%5,%6,%7},{%8,%9},{%10,%11,%12,%13};"
    : "=f"(d[0]),"=f"(d[1]),"=f"(d[2]),"=f"(d[3])
    : "r"(a[0]),"r"(a[1]),"r"(a[2]),"r"(a[3]), "r"(b[0]),"r"(b[1]),
      "f"(c[0]),"f"(c[1]),"f"(c[2]),"f"(c[3]));
}
__device__ __forceinline__ void lds64(uint32_t& x, uint32_t& y, uint32_t a){
  asm volatile("ld.shared.v2.b32 {%0,%1},[%2];" : "=r"(x), "=r"(y) : "r"(a));
}
__device__ __forceinline__ uint32_t smem_u32(const void* p){
  uint32_t a; asm("{ .reg .u64 t; cvta.to.shared.u64 t, %1; cvt.u32.u64 %0, t; }" : "=r"(a) : "l"(p));
  return a;
}
// position of k within permuted 8-chunk: [k0,k4,k1,k5,k2,k6,k3,k7]
__device__ __forceinline__ int pperm(int k){
  int km = k & 7; return (k & ~7) + ((km < 4) ? 2*km : 2*(km-4)+1);
}

__global__ void __launch_bounds__(NTHR,1) vq_main(const float* __restrict__ x,
                                                  const float* __restrict__ emb,
                                                  float* __restrict__ out, int out_size){
  extern __shared__ float sm[];
  float* Hs = sm;
  float* Ls = sm + HWORDS;
  __shared__ float swr[WPB];
  __shared__ int slast;
  const uint32_t sbase = smem_u32(sm);
  const uint32_t Hb = sbase, Lb = sbase + HWORDS*4;
  const int tid = threadIdx.x, lane = tid & 31, wid = tid >> 5;
  const int q = lane & 3, r0 = lane >> 2;
  const uint32_t lanoff = (r0*24 + 2*q)*4;

  // build codebook h/l tf32 splits: two packed regions, row stride 24 words (conflict-free)
  for (int k = tid; k < 1024; k += NTHR){
    float e[Dd]; float nh;
    if (k < Kk){
      float s = 0.f;
      #pragma unroll
      for (int d = 0; d < Dd; d++){ e[d] = __ldg(emb + k*Dd + d); s = fmaf(e[d], e[d], s); }
      nh = -0.5f*s;
    } else {
      #pragma unroll
      for (int d = 0; d < Dd; d++) e[d] = 0.f;
      nh = -1e30f;
    }
    #pragma unroll
    for (int kk = 0; kk < 24; kk++){
      float v = (kk < Dd) ? e[kk] : ((kk == Dd) ? nh : 0.f);
      uint32_t h = tf32h(v);
      Hs[k*24 + pperm(kk)] = __uint_as_float(h);
      Ls[k*24 + pperm(kk)] = __uint_as_float(tf32h(v - __uint_as_float(h)));
    }
  }
  __syncthreads();

  float klacc = 0.f;
  int u = blockIdx.x*WPB + wid;
  while (u < NUNITS){
    // A fragments: rows r0, r0+8; k = q + 4m, m = 0..5
    uint32_t ah[3][4], al[3][4];
    {
      const int n0 = u*16 + r0, n1 = n0 + 8;
      const float* p0 = x + (size_t)(n0 >> 12)*(Dd*Ll) + (n0 & (Ll-1));
      const float* p1 = x + (size_t)(n1 >> 12)*(Dd*Ll) + (n1 & (Ll-1));
      #pragma unroll
      for (int m = 0; m < 6; m++){
        const int k = q + 4*m;
        float v0 = (k < Dd) ? __ldg(p0 + k*Ll) : ((k == Dd) ? 1.f : 0.f);
        float v1 = (k < Dd) ? __ldg(p1 + k*Ll) : ((k == Dd) ? 1.f : 0.f);
        const int c = m >> 1, hi = (m & 1) ? 2 : 0;
        uint32_t h0 = tf32h(v0), h1 = tf32h(v1);
        ah[c][hi] = h0; ah[c][hi+1] = h1;
        al[c][hi]   = tf32h(v0 - __uint_as_float(h0));
        al[c][hi+1] = tf32h(v1 - __uint_as_float(h1));
      }
    }

    float best0 = -3.4e38f, best1 = -3.4e38f;
    int   idx0 = 0, idx1 = 0;
    const float z[4] = {0.f, 0.f, 0.f, 0.f};

    // double-buffered B fragments + accumulators (software pipeline, depth 2)
    uint32_t bh[2][3][2], bl[2][3][2];
    float dA[2][4], dB[2][4], dC[2][4];

    #define LOADB(p, nbv) do { \
      const uint32_t rwo = (uint32_t)(nbv)*768u + lanoff; \
      _Pragma("unroll") \
      for (int c = 0; c < 3; c++){ \
        lds64(bh[p][c][0], bh[p][c][1], Hb + rwo + c*32); \
        lds64(bl[p][c][0], bl[p][c][1], Lb + rwo + c*32); \
      } } while(0)
    #define MMA9(p) do { \
      mma_tf32(dA[p], ah[0], bh[p][0], z); \
      mma_tf32(dB[p], ah[0], bl[p][0], z); \
      mma_tf32(dC[p], al[0], bh[p][0], z); \
      mma_tf32(dA[p], ah[1], bh[p][1], dA[p]); \
      mma_tf32(dB[p], ah[1], bl[p][1], dB[p]); \
      mma_tf32(dC[p], al[1], bh[p][1], dC[p]); \
      mma_tf32(dA[p], ah[2], bh[p][2], dA[p]); \
      mma_tf32(dB[p], ah[2], bl[p][2], dB[p]); \
      mma_tf32(dC[p], al[2], bh[p][2], dC[p]); \
      } while(0)
    #define CMP(p, nbv) do { \
      float d4[4]; \
      _Pragma("unroll") \
      for (int j = 0; j < 4; j++) d4[j] = dA[p][j] + (dB[p][j] + dC[p][j]); \
      const int c0 = (nbv)*8 + 2*q; \
      if (d4[0] > best0){ best0 = d4[0]; idx0 = c0; } \
      if (d4[1] > best0){ best0 = d4[1]; idx0 = c0+1; } \
      if (d4[2] > best1){ best1 = d4[2]; idx1 = c0; } \
      if (d4[3] > best1){ best1 = d4[3]; idx1 = c0+1; } \
      } while(0)

    LOADB(0, 0); MMA9(0);
    #pragma unroll 1
    for (int nb = 0; nb < 126; nb += 2){
      LOADB(1, nb+1); MMA9(1);      // fill pipe before consuming nb
      CMP(0, nb);
      LOADB(0, nb+2); MMA9(0);
      CMP(1, nb+1);
    }
    LOADB(1, 127); MMA9(1);
    CMP(0, 126);
    CMP(1, 127);

    // reduce across the 4 lanes sharing each row
    #pragma unroll
    for (int off = 1; off <= 2; off <<= 1){
      float s0 = __shfl_xor_sync(0xFFFFFFFFu, best0, off);
      int   i0 = __shfl_xor_sync(0xFFFFFFFFu, idx0,  off);
      if (s0 > best0 || (s0 == best0 && i0 < idx0)){ best0 = s0; idx0 = i0; }
      float s1 = __shfl_xor_sync(0xFFFFFFFFu, best1, off);
      int   i1 = __shfl_xor_sync(0xFFFFFFFFu, idx1,  off);
      if (s1 > best1 || (s1 == best1 && i1 < idx1)){ best1 = s1; idx1 = i1; }
    }
    // distribute: lane j<16 gets code for point u*16+j
    const int src = (lane & 7)*4;
    const int c0 = __shfl_sync(0xFFFFFFFFu, idx0, src);
    const int c1 = __shfl_sync(0xFFFFFFFFu, idx1, src);

    if (lane < 16){
      const int code = (lane < 8) ? c0 : c1;
      const int n = u*16 + lane;
      const int bb = n >> 12, l = n & (Ll-1);
      const float* xp = x + (size_t)bb*(Dd*Ll) + l;
      float* op = out + (size_t)bb*(Dd*Ll) + l;
      float xv[Dd], qv[Dd];
      #pragma unroll
      for (int d = 0; d < Dd; d++){
        xv[d] = __ldg(xp + d*Ll);
        const int pp = code*24 + pperm(d);
        qv[d] = Hs[pp] + Ls[pp];
      }
      #pragma unroll
      for (int d = 0; d < Dd; d++) op[d*Ll] = xv[d] + (qv[d] - xv[d]);
      atomicAdd(&g_hist[code], 1);

      float mx = xv[0], mq = qv[0];
      #pragma unroll
      for (int d = 1; d < Dd; d++){ mx = fmaxf(mx, xv[d]); mq = fmaxf(mq, qv[d]); }
      float Sx = 0.f, Sq = 0.f, A = 0.f, Cr = 0.f;
      #pragma unroll
      for (int d = 0; d < Dd; d++){
        float xs = xv[d] - mx;
        float ex = __expf(xs), eq = __expf(qv[d] - mq);
        Sx += ex; Sq += eq;
        A  = fmaf(ex, xs, A);
        Cr = fmaf(ex, eq, Cr);
      }
      klacc += A/Sx - __logf(Sx) - Cr/(Sx*Sq);
    }

    if (lane == 0) u = NWARPS + atomicAdd(&g_work, 1);
    u = __shfl_sync(0xFFFFFFFFu, u, 0);
  }

  // block-level KL reduction, one atomic per block
  #pragma unroll
  for (int off = 16; off; off >>= 1) klacc += __shfl_xor_sync(0xFFFFFFFFu, klacc, off);
  if (lane == 0) swr[wid] = klacc;
  __syncthreads();
  if (tid == 0){
    float s = 0.f;
    #pragma unroll
    for (int w = 0; w < WPB; w++) s += swr[w];
    atomicAdd(&g_kl, s);
  }

  __threadfence();
  __syncthreads();
  if (tid == 0) slast = (atomicAdd(&g_done, 1) == NBLK - 1);
  __syncthreads();
  if (slast){
    float s = 0.f;
    for (int k = tid; k < Kk; k += NTHR){
      float a = (float)(*(volatile int*)&g_hist[k]) * (1.f/(float)Nn);
      s += a * logf(a + 1e-10f);
      g_hist[k] = 0;
    }
    #pragma unroll
    for (int off = 16; off; off >>= 1) s += __shfl_xor_sync(0xFFFFFFFFu, s, off);
    if (lane == 0) swr[wid] = s;
    __syncthreads();
    if (tid == 0){
      float t = 0.f;
      #pragma unroll
      for (int w = 0; w < WPB; w++) t += swr[w];
      if (out_size >= NDLs + 2){
        out[NDLs]     = 0.1f * ((*(volatile float*)&g_kl) / (float)Bb);
        out[NDLs + 1] = expf(-t);
      }
      g_kl = 0.f; g_done = 0; g_work = 0;
    }
  }
}

extern "C" void kernel_launch(void* const* d_in, const int* in_sizes, int n_in,
                              void* d_out, int out_size){
  const float* x   = (const float*)d_in[0];
  const float* emb = (const float*)d_in[1];
  float* out = (float*)d_out;
  cudaFuncSetAttribute(vq_main, cudaFuncAttributeMaxDynamicSharedMemorySize, SMEM_BYTES);
  vq_main<<<NBLK, NTHR, SMEM_BYTES>>>(x, emb, out, out_size);
}

// round 10
// speedup vs baseline: 1.0127x; 1.0127x over previous
#include <cuda_runtime.h>
#include <cstdint>

#define Bb 32
#define Dd 20
#define Ll 4096
#define Kk 1000
#define Nn (Bb*Ll)
#define NDLs (Bb*Dd*Ll)
#define NUNITS (Nn/16)          // 8192 m16 tiles
#define NBLK 148
#define WPB 32
#define NTHR (WPB*32)           // 1024
#define NWARPS (NBLK*WPB)       // 4736
#define HWORDS (1024*24)
#define SMEM_BYTES (2*HWORDS*4) // 196608 B

__device__ int   g_work;
__device__ float g_kl;
__device__ int   g_hist[Kk];
__device__ int   g_done;

__device__ __forceinline__ uint32_t tf32h(float v){
  uint32_t r; asm("cvt.rna.tf32.f32 %0, %1;" : "=r"(r) : "f"(v)); return r;
}
__device__ __forceinline__ void mma_tf32(float* d, const uint32_t* a, const uint32_t* b, const float* c){
  asm volatile("mma.sync.aligned.m16n8k8.row.col.f32.tf32.tf32.f32 "
    "{%0,%1,%2,%3},{%4,%5,%6,%7},{%8,%9},{%10,%11,%12,%13};"
    : "=f"(d[0]),"=f"(d[1]),"=f"(d[2]),"=f"(d[3])
    : "r"(a[0]),"r"(a[1]),"r"(a[2]),"r"(a[3]), "r"(b[0]),"r"(b[1]),
      "f"(c[0]),"f"(c[1]),"f"(c[2]),"f"(c[3]));
}
__device__ __forceinline__ void lds64(uint32_t& x, uint32_t& y, uint32_t a){
  asm volatile("ld.shared.v2.b32 {%0,%1},[%2];" : "=r"(x), "=r"(y) : "r"(a));
}
__device__ __forceinline__ uint32_t smem_u32(const void* p){
  uint32_t a; asm("{ .reg .u64 t; cvta.to.shared.u64 t, %1; cvt.u32.u64 %0, t; }" : "=r"(a) : "l"(p));
  return a;
}
// position of k within permuted 8-chunk: [k0,k4,k1,k5,k2,k6,k3,k7]
__device__ __forceinline__ int pperm(int k){
  int km = k & 7; return (k & ~7) + ((km < 4) ? 2*km : 2*(km-4)+1);
}

__global__ void __launch_bounds__(NTHR,1) vq_main(const float* __restrict__ x,
                                                  const float* __restrict__ emb,
                                                  float* __restrict__ out, int out_size){
  extern __shared__ float sm[];
  float* Hs = sm;
  float* Ls = sm + HWORDS;
  __shared__ float swr[WPB];
  __shared__ int slast;
  const uint32_t sbase = smem_u32(sm);
  const uint32_t Hb = sbase, Lb = sbase + HWORDS*4;
  const int tid = threadIdx.x, lane = tid & 31, wid = tid >> 5;
  const int q = lane & 3, r0 = lane >> 2;
  const uint32_t lanoff = (r0*24 + 2*q)*4;

  // build codebook h/l tf32 splits: two packed regions, row stride 24 words (conflict-free)
  for (int k = tid; k < 1024; k += NTHR){
    float e[Dd]; float nh;
    if (k < Kk){
      float s = 0.f;
      #pragma unroll
      for (int d = 0; d < Dd; d++){ e[d] = __ldg(emb + k*Dd + d); s = fmaf(e[d], e[d], s); }
      nh = -0.5f*s;
    } else {
      #pragma unroll
      for (int d = 0; d < Dd; d++) e[d] = 0.f;
      nh = -1e30f;
    }
    #pragma unroll
    for (int kk = 0; kk < 24; kk++){
      float v = (kk < Dd) ? e[kk] : ((kk == Dd) ? nh : 0.f);
      uint32_t h = tf32h(v);
      Hs[k*24 + pperm(kk)] = __uint_as_float(h);
      Ls[k*24 + pperm(kk)] = __uint_as_float(tf32h(v - __uint_as_float(h)));
    }
  }
  __syncthreads();

  float klacc = 0.f;
  int u = blockIdx.x*WPB + wid;
  while (u < NUNITS){
    // A fragments: rows r0, r0+8; k = q + 4m, m = 0..5
    uint32_t ah[3][4], al[3][4];
    {
      const int n0 = u*16 + r0, n1 = n0 + 8;
      const float* p0 = x + (size_t)(n0 >> 12)*(Dd*Ll) + (n0 & (Ll-1));
      const float* p1 = x + (size_t)(n1 >> 12)*(Dd*Ll) + (n1 & (Ll-1));
      #pragma unroll
      for (int m = 0; m < 6; m++){
        const int k = q + 4*m;
        float v0 = (k < Dd) ? __ldg(p0 + k*Ll) : ((k == Dd) ? 1.f : 0.f);
        float v1 = (k < Dd) ? __ldg(p1 + k*Ll) : ((k == Dd) ? 1.f : 0.f);
        const int c = m >> 1, hi = (m & 1) ? 2 : 0;
        uint32_t h0 = tf32h(v0), h1 = tf32h(v1);
        ah[c][hi] = h0; ah[c][hi+1] = h1;
        al[c][hi]   = tf32h(v0 - __uint_as_float(h0));
        al[c][hi+1] = tf32h(v1 - __uint_as_float(h1));
      }
    }

    float best0 = -3.4e38f, best1 = -3.4e38f;
    int   idx0 = 0, idx1 = 0;
    const float z[4] = {0.f, 0.f, 0.f, 0.f};

    #pragma unroll 1
    for (int nb = 0; nb < 128; nb++){
      const uint32_t rwo = (uint32_t)nb*768u + lanoff;   // row word offset (bytes)
      uint32_t bh[3][2], bl[3][2];
      #pragma unroll
      for (int c = 0; c < 3; c++){
        lds64(bh[c][0], bh[c][1], Hb + rwo + c*32);
        lds64(bl[c][0], bl[c][1], Lb + rwo + c*32);
      }
      float dA[4], dB[4], dC[4];
      mma_tf32(dA, ah[0], bh[0], z);
      mma_tf32(dB, ah[0], bl[0], z);
      mma_tf32(dC, al[0], bh[0], z);
      mma_tf32(dA, ah[1], bh[1], dA);
      mma_tf32(dB, ah[1], bl[1], dB);
      mma_tf32(dC, al[1], bh[1], dC);
      mma_tf32(dA, ah[2], bh[2], dA);
      mma_tf32(dB, ah[2], bl[2], dB);
      mma_tf32(dC, al[2], bh[2], dC);
      float d4[4];
      #pragma unroll
      for (int j = 0; j < 4; j++) d4[j] = dA[j] + (dB[j] + dC[j]);

      const int c0 = nb*8 + 2*q;
      if (d4[0] > best0){ best0 = d4[0]; idx0 = c0; }
      if (d4[1] > best0){ best0 = d4[1]; idx0 = c0+1; }
      if (d4[2] > best1){ best1 = d4[2]; idx1 = c0; }
      if (d4[3] > best1){ best1 = d4[3]; idx1 = c0+1; }
    }

    // reduce across the 4 lanes sharing each row
    #pragma unroll
    for (int off = 1; off <= 2; off <<= 1){
      float s0 = __shfl_xor_sync(0xFFFFFFFFu, best0, off);
      int   i0 = __shfl_xor_sync(0xFFFFFFFFu, idx0,  off);
      if (s0 > best0 || (s0 == best0 && i0 < idx0)){ best0 = s0; idx0 = i0; }
      float s1 = __shfl_xor_sync(0xFFFFFFFFu, best1, off);
      int   i1 = __shfl_xor_sync(0xFFFFFFFFu, idx1,  off);
      if (s1 > best1 || (s1 == best1 && i1 < idx1)){ best1 = s1; idx1 = i1; }
    }
    // distribute: lane j<16 gets code for point u*16+j
    const int src = (lane & 7)*4;
    const int c0 = __shfl_sync(0xFFFFFFFFu, idx0, src);
    const int c1 = __shfl_sync(0xFFFFFFFFu, idx1, src);

    if (lane < 16){
      const int code = (lane < 8) ? c0 : c1;
      const int n = u*16 + lane;
      const int bb = n >> 12, l = n & (Ll-1);
      const float* xp = x + (size_t)bb*(Dd*Ll) + l;
      float* op = out + (size_t)bb*(Dd*Ll) + l;

      // streaming two-pass epilogue (register-lean for 64-reg budget)
      float mx = -3.4e38f, mq = -3.4e38f;
      #pragma unroll 4
      for (int d = 0; d < Dd; d++){
        float xv = __ldg(xp + d*Ll);
        const int pp = code*24 + pperm(d);
        float qv = Hs[pp] + Ls[pp];
        mx = fmaxf(mx, xv); mq = fmaxf(mq, qv);
      }
      float Sx = 0.f, Sq = 0.f, A = 0.f, Cr = 0.f;
      #pragma unroll 4
      for (int d = 0; d < Dd; d++){
        float xv = __ldg(xp + d*Ll);
        const int pp = code*24 + pperm(d);
        float qv = Hs[pp] + Ls[pp];
        op[d*Ll] = xv + (qv - xv);
        float xs = xv - mx;
        float ex = __expf(xs), eq = __expf(qv - mq);
        Sx += ex; Sq += eq;
        A  = fmaf(ex, xs, A);
        Cr = fmaf(ex, eq, Cr);
      }
      klacc += A/Sx - __logf(Sx) - Cr/(Sx*Sq);
      atomicAdd(&g_hist[code], 1);
    }

    if (lane == 0) u = NWARPS + atomicAdd(&g_work, 1);
    u = __shfl_sync(0xFFFFFFFFu, u, 0);
  }

  // block-level KL reduction, one atomic per block
  #pragma unroll
  for (int off = 16; off; off >>= 1) klacc += __shfl_xor_sync(0xFFFFFFFFu, klacc, off);
  if (lane == 0) swr[wid] = klacc;
  __syncthreads();
  if (tid == 0){
    float s = 0.f;
    #pragma unroll
    for (int w = 0; w < WPB; w++) s += swr[w];
    atomicAdd(&g_kl, s);
  }

  __threadfence();
  __syncthreads();
  if (tid == 0) slast = (atomicAdd(&g_done, 1) == NBLK - 1);
  __syncthreads();
  if (slast){
    float s = 0.f;
    for (int k = tid; k < Kk; k += NTHR){
      float a = (float)(*(volatile int*)&g_hist[k]) * (1.f/(float)Nn);
      s += a * logf(a + 1e-10f);
      g_hist[k] = 0;
    }
    #pragma unroll
    for (int off = 16; off; off >>= 1) s += __shfl_xor_sync(0xFFFFFFFFu, s, off);
    if (lane == 0) swr[wid] = s;
    __syncthreads();
    if (tid == 0){
      float t = 0.f;
      #pragma unroll
      for (int w = 0; w < WPB; w++) t += swr[w];
      if (out_size >= NDLs + 2){
        out[NDLs]     = 0.1f * ((*(volatile float*)&g_kl) / (float)Bb);
        out[NDLs + 1] = expf(-t);
      }
      g_kl = 0.f; g_done = 0; g_work = 0;
    }
  }
}

extern "C" void kernel_launch(void* const* d_in, const int* in_sizes, int n_in,
                              void* d_out, int out_size){
  const float* x   = (const float*)d_in[0];
  const float* emb = (const float*)d_in[1];
  float* out = (float*)d_out;
  cudaFuncSetAttribute(vq_main, cudaFuncAttributeMaxDynamicSharedMemorySize, SMEM_BYTES);
  vq_main<<<NBLK, NTHR, SMEM_BYTES>>>(x, emb, out, out_size);
}

// round 11
// speedup vs baseline: 1.3339x; 1.3171x over previous
#include <cuda_runtime.h>
#include <cuda_fp16.h>
#include <cstdint>

#define Bb 32
#define Dd 20
#define Ll 4096
#define Kk 1000
#define Nn (Bb*Ll)
#define NDLs (Bb*Dd*Ll)
#define NUNITS (Nn/16)          // 8192 m16 tiles
#define NBLK 148
#define WPB 32
#define NTHR (WPB*32)           // 1024
#define NWARPS (NBLK*WPB)       // 4736
#define ROWW 20                 // words per code row (40 halves, stride coprime-ish: g*20+tg spans all banks)
#define RWORDS (1024*ROWW)
#define SMEM_BYTES (2*RWORDS*4) // 163840 B

__device__ int   g_work;
__device__ float g_kl;
__device__ int   g_hist[Kk];
__device__ int   g_done;

__device__ __forceinline__ void mma_f16(float* d, uint32_t a0, uint32_t a1, uint32_t a2, uint32_t a3,
                                        uint32_t b0, uint32_t b1, const float* c){
  asm volatile("mma.sync.aligned.m16n8k16.row.col.f32.f16.f16.f32 "
    "{%0,%1,%2,%3},{%4,%5,%6,%7},{%8,%9},{%10,%11,%12,%13};"
    : "=f"(d[0]),"=f"(d[1]),"=f"(d[2]),"=f"(d[3])
    : "r"(a0),"r"(a1),"r"(a2),"r"(a3), "r"(b0),"r"(b1),
      "f"(c[0]),"f"(c[1]),"f"(c[2]),"f"(c[3]));
}
__device__ __forceinline__ void lds32(uint32_t& v, uint32_t a){
  asm volatile("ld.shared.b32 %0,[%1];" : "=r"(v) : "r"(a));
}
__device__ __forceinline__ uint32_t smem_u32(const void* p){
  uint32_t a; asm("{ .reg .u64 t; cvta.to.shared.u64 t, %1; cvt.u32.u64 %0, t; }" : "=r"(a) : "l"(p));
  return a;
}
__device__ __forceinline__ uint32_t packh(__half a, __half b){
  __half2 t = __halves2half2(a, b); return *(uint32_t*)&t;
}

__global__ void __launch_bounds__(NTHR,1) vq_main(const float* __restrict__ x,
                                                  const float* __restrict__ emb,
                                                  float* __restrict__ out, int out_size){
  extern __shared__ __half smh[];
  __half* Hh = smh;               // [1024*40] high parts, k-natural order, row stride 40 halves
  __half* Hm = smh + 2*RWORDS;    // [1024*40] mid (residual) parts
  __shared__ float swr[WPB];
  __shared__ int slast;
  const uint32_t sbase = smem_u32(smh);
  const uint32_t HB = sbase, MB = sbase + RWORDS*4;
  const int tid = threadIdx.x, lane = tid & 31, wid = tid >> 5;
  const int tg = lane & 3, g = lane >> 2;
  const uint32_t lanoff = (g*ROWW + tg)*4;

  // codebook fp16 h/m splits (aug k=20 -> -0.5||e||^2; pads zero; pad-codes bias -60000)
  for (int k = tid; k < 1024; k += NTHR){
    float e[Dd]; float nh;
    if (k < Kk){
      float s = 0.f;
      #pragma unroll
      for (int d = 0; d < Dd; d++){ e[d] = __ldg(emb + k*Dd + d); s = fmaf(e[d], e[d], s); }
      nh = -0.5f*s;
    } else {
      #pragma unroll
      for (int d = 0; d < Dd; d++) e[d] = 0.f;
      nh = -60000.f;
    }
    #pragma unroll
    for (int kk = 0; kk < 24; kk++){
      float v = (kk < Dd) ? e[kk] : ((kk == Dd) ? nh : 0.f);
      __half h = __float2half_rn(v);
      Hh[k*40 + kk] = h;
      Hm[k*40 + kk] = __float2half_rn(v - __half2float(h));
    }
  }
  __syncthreads();

  float klacc = 0.f;
  int u = blockIdx.x*WPB + wid;
  while (u < NUNITS){
    // A fragments (fp16 h/m): rows g, g+8; k = 2tg+{0,1,8,9,16,17}
    uint32_t AH[6], AM[6];
    {
      const int n0 = u*16 + g, n1 = n0 + 8;
      const float* p0 = x + (size_t)(n0 >> 12)*(Dd*Ll) + (n0 & (Ll-1));
      const float* p1 = x + (size_t)(n1 >> 12)*(Dd*Ll) + (n1 & (Ll-1));
      #pragma unroll
      for (int j = 0; j < 3; j++){               // k-pair groups: base 2tg + {0,8,16}
        const int ka = 2*tg + j*8, kb = ka + 1;
        float va0 = (ka < Dd) ? __ldg(p0 + ka*Ll) : ((ka == Dd) ? 1.f : 0.f);
        float vb0 = (kb < Dd) ? __ldg(p0 + kb*Ll) : ((kb == Dd) ? 1.f : 0.f);
        float va1 = (ka < Dd) ? __ldg(p1 + ka*Ll) : ((ka == Dd) ? 1.f : 0.f);
        float vb1 = (kb < Dd) ? __ldg(p1 + kb*Ll) : ((kb == Dd) ? 1.f : 0.f);
        __half ha0 = __float2half_rn(va0), hb0 = __float2half_rn(vb0);
        __half ha1 = __float2half_rn(va1), hb1 = __float2half_rn(vb1);
        AH[2*j]   = packh(ha0, hb0);
        AH[2*j+1] = packh(ha1, hb1);
        AM[2*j]   = packh(__float2half_rn(va0 - __half2float(ha0)), __float2half_rn(vb0 - __half2float(hb0)));
        AM[2*j+1] = packh(__float2half_rn(va1 - __half2float(ha1)), __float2half_rn(vb1 - __half2float(hb1)));
      }
    }
    const uint32_t ZR = 0u;

    float best0 = -3.4e38f, best1 = -3.4e38f;
    int   idx0 = 0, idx1 = 0;
    const float z[4] = {0.f, 0.f, 0.f, 0.f};

    #pragma unroll 2
    for (int nb = 0; nb < 128; nb++){
      const uint32_t rb = (uint32_t)nb*(8u*ROWW*4u) + lanoff;
      uint32_t bh0, bh1, bh2, bm0, bm1, bm2;
      lds32(bh0, HB + rb); lds32(bh1, HB + rb + 16); lds32(bh2, HB + rb + 32);
      lds32(bm0, MB + rb); lds32(bm1, MB + rb + 16); lds32(bm2, MB + rb + 32);

      float dA[4], dB[4], dC[4];
      mma_f16(dA, AH[0], AH[1], AH[2], AH[3], bh0, bh1, z);     // hh c1
      mma_f16(dB, AH[0], AH[1], AH[2], AH[3], bm0, bm1, z);     // hm c1
      mma_f16(dC, AM[0], AM[1], AM[2], AM[3], bh0, bh1, z);     // mh c1
      mma_f16(dA, AH[4], AH[5], ZR, ZR, bh2, ZR, dA);           // hh c2
      mma_f16(dB, AH[4], AH[5], ZR, ZR, bm2, ZR, dB);           // hm c2
      mma_f16(dC, AM[4], AM[5], ZR, ZR, bh2, ZR, dC);           // mh c2
      float d4[4];
      #pragma unroll
      for (int j = 0; j < 4; j++) d4[j] = dA[j] + (dB[j] + dC[j]);

      const int c0 = nb*8 + 2*tg;
      if (d4[0] > best0){ best0 = d4[0]; idx0 = c0; }
      if (d4[1] > best0){ best0 = d4[1]; idx0 = c0+1; }
      if (d4[2] > best1){ best1 = d4[2]; idx1 = c0; }
      if (d4[3] > best1){ best1 = d4[3]; idx1 = c0+1; }
    }

    // reduce across the 4 lanes sharing each row
    #pragma unroll
    for (int off = 1; off <= 2; off <<= 1){
      float s0 = __shfl_xor_sync(0xFFFFFFFFu, best0, off);
      int   i0 = __shfl_xor_sync(0xFFFFFFFFu, idx0,  off);
      if (s0 > best0 || (s0 == best0 && i0 < idx0)){ best0 = s0; idx0 = i0; }
      float s1 = __shfl_xor_sync(0xFFFFFFFFu, best1, off);
      int   i1 = __shfl_xor_sync(0xFFFFFFFFu, idx1,  off);
      if (s1 > best1 || (s1 == best1 && i1 < idx1)){ best1 = s1; idx1 = i1; }
    }
    // distribute: lane j<16 gets code for point u*16+j
    const int src = (lane & 7)*4;
    const int c0s = __shfl_sync(0xFFFFFFFFu, idx0, src);
    const int c1s = __shfl_sync(0xFFFFFFFFu, idx1, src);

    if (lane < 16){
      const int code = (lane < 8) ? c0s : c1s;
      const int n = u*16 + lane;
      const int bb = n >> 12, l = n & (Ll-1);
      const float* xp = x + (size_t)bb*(Dd*Ll) + l;
      float* op = out + (size_t)bb*(Dd*Ll) + l;

      float mx = -3.4e38f, mq = -3.4e38f;
      #pragma unroll 4
      for (int d = 0; d < Dd; d++){
        float xv = __ldg(xp + d*Ll);
        float qv = __half2float(Hh[code*40 + d]) + __half2float(Hm[code*40 + d]);
        mx = fmaxf(mx, xv); mq = fmaxf(mq, qv);
      }
      float Sx = 0.f, Sq = 0.f, A = 0.f, Cr = 0.f;
      #pragma unroll 4
      for (int d = 0; d < Dd; d++){
        float xv = __ldg(xp + d*Ll);
        float qv = __half2float(Hh[code*40 + d]) + __half2float(Hm[code*40 + d]);
        op[d*Ll] = xv + (qv - xv);
        float xs = xv - mx;
        float ex = __expf(xs), eq = __expf(qv - mq);
        Sx += ex; Sq += eq;
        A  = fmaf(ex, xs, A);
        Cr = fmaf(ex, eq, Cr);
      }
      klacc += A/Sx - __logf(Sx) - Cr/(Sx*Sq);
      atomicAdd(&g_hist[code], 1);
    }

    if (lane == 0) u = NWARPS + atomicAdd(&g_work, 1);
    u = __shfl_sync(0xFFFFFFFFu, u, 0);
  }

  // block-level KL reduction, one atomic per block
  #pragma unroll
  for (int off = 16; off; off >>= 1) klacc += __shfl_xor_sync(0xFFFFFFFFu, klacc, off);
  if (lane == 0) swr[wid] = klacc;
  __syncthreads();
  if (tid == 0){
    float s = 0.f;
    #pragma unroll
    for (int w = 0; w < WPB; w++) s += swr[w];
    atomicAdd(&g_kl, s);
  }

  __threadfence();
  __syncthreads();
  if (tid == 0) slast = (atomicAdd(&g_done, 1) == NBLK - 1);
  __syncthreads();
  if (slast){
    float s = 0.f;
    for (int k = tid; k < Kk; k += NTHR){
      float a = (float)(*(volatile int*)&g_hist[k]) * (1.f/(float)Nn);
      s += a * logf(a + 1e-10f);
      g_hist[k] = 0;
    }
    #pragma unroll
    for (int off = 16; off; off >>= 1) s += __shfl_xor_sync(0xFFFFFFFFu, s, off);
    if (lane == 0) swr[wid] = s;
    __syncthreads();
    if (tid == 0){
      float t = 0.f;
      #pragma unroll
      for (int w = 0; w < WPB; w++) t += swr[w];
      if (out_size >= NDLs + 2){
        out[NDLs]     = 0.1f * ((*(volatile float*)&g_kl) / (float)Bb);
        out[NDLs + 1] = expf(-t);
      }
      g_kl = 0.f; g_done = 0; g_work = 0;
    }
  }
}

extern "C" void kernel_launch(void* const* d_in, const int* in_sizes, int n_in,
                              void* d_out, int out_size){
  const float* x   = (const float*)d_in[0];
  const float* emb = (const float*)d_in[1];
  float* out = (float*)d_out;
  cudaFuncSetAttribute(vq_main, cudaFuncAttributeMaxDynamicSharedMemorySize, SMEM_BYTES);
  vq_main<<<NBLK, NTHR, SMEM_BYTES>>>(x, emb, out, out_size);
}

// round 13
// speedup vs baseline: 1.6650x; 1.2483x over previous
#include <cuda_runtime.h>
#include <cuda_fp16.h>
#include <cstdint>

#define Bb 32
#define Dd 20
#define Ll 4096
#define Kk 1000
#define Nn (Bb*Ll)
#define NDLs (Bb*Dd*Ll)
#define NUNITS (Nn/16)          // 8192 m16 tiles
#define NBLK 148
#define WPB 32
#define NTHR (WPB*32)           // 1024
#define NWARPS (NBLK*WPB)       // 4736
#define ROWW 20                 // words per code row (40 halves)
#define RWORDS (1024*ROWW)
#define SMEM_BYTES (2*RWORDS*4) // 163840 B

__device__ int   g_work;
__device__ float g_kl;
__device__ int   g_hist[Kk];
__device__ int   g_done;

__device__ __forceinline__ void mma_f16(float* d, uint32_t a0, uint32_t a1, uint32_t a2, uint32_t a3,
                                        uint32_t b0, uint32_t b1, const float* c){
  asm volatile("mma.sync.aligned.m16n8k16.row.col.f32.f16.f16.f32 "
    "{%0,%1,%2,%3},{%4,%5,%6,%7},{%8,%9},{%10,%11,%12,%13};"
    : "=f"(d[0]),"=f"(d[1]),"=f"(d[2]),"=f"(d[3])
    : "r"(a0),"r"(a1),"r"(a2),"r"(a3), "r"(b0),"r"(b1),
      "f"(c[0]),"f"(c[1]),"f"(c[2]),"f"(c[3]));
}
__device__ __forceinline__ void mma_f16_k8(float* d, uint32_t a0, uint32_t a1,
                                           uint32_t b0, const float* c){
  asm volatile("mma.sync.aligned.m16n8k8.row.col.f32.f16.f16.f32 "
    "{%0,%1,%2,%3},{%4,%5},{%6},{%7,%8,%9,%10};"
    : "=f"(d[0]),"=f"(d[1]),"=f"(d[2]),"=f"(d[3])
    : "r"(a0),"r"(a1), "r"(b0),
      "f"(c[0]),"f"(c[1]),"f"(c[2]),"f"(c[3]));
}
__device__ __forceinline__ void lds32(uint32_t& v, uint32_t a){
  asm volatile("ld.shared.b32 %0,[%1];" : "=r"(v) : "r"(a));
}
__device__ __forceinline__ uint32_t smem_u32(const void* p){
  uint32_t a; asm("{ .reg .u64 t; cvta.to.shared.u64 t, %1; cvt.u32.u64 %0, t; }" : "=r"(a) : "l"(p));
  return a;
}
__device__ __forceinline__ uint32_t packh(__half a, __half b){
  __half2 t = __halves2half2(a, b); return *(uint32_t*)&t;
}

__global__ void __launch_bounds__(NTHR,1) vq_main(const float* __restrict__ x,
                                                  const float* __restrict__ emb,
                                                  float* __restrict__ out, int out_size){
  extern __shared__ __half smh[];
  __half* Hh = smh;               // [1024*40] high parts, k-natural order, row stride 40 halves
  __half* Hm = smh + 2*RWORDS;    // [1024*40] mid (residual) parts
  __shared__ float swr[WPB];
  __shared__ int slast;
  const uint32_t sbase = smem_u32(smh);
  const uint32_t HB = sbase, MB = sbase + RWORDS*4;
  const int tid = threadIdx.x, lane = tid & 31, wid = tid >> 5;
  const int tg = lane & 3, g = lane >> 2;
  const uint32_t lanoff = (g*ROWW + tg)*4;

  // codebook fp16 h/m splits (aug k=20 -> -0.5||e||^2; pads zero; pad-codes bias -60000)
  for (int k = tid; k < 1024; k += NTHR){
    float e[Dd]; float nh;
    if (k < Kk){
      float s = 0.f;
      #pragma unroll
      for (int d = 0; d < Dd; d++){ e[d] = __ldg(emb + k*Dd + d); s = fmaf(e[d], e[d], s); }
      nh = -0.5f*s;
    } else {
      #pragma unroll
      for (int d = 0; d < Dd; d++) e[d] = 0.f;
      nh = -60000.f;
    }
    #pragma unroll
    for (int kk = 0; kk < 24; kk++){
      float v = (kk < Dd) ? e[kk] : ((kk == Dd) ? nh : 0.f);
      __half h = __float2half_rn(v);
      Hh[k*40 + kk] = h;
      Hm[k*40 + kk] = __float2half_rn(v - __half2float(h));
    }
  }
  __syncthreads();

  float klacc = 0.f;
  int u = blockIdx.x*WPB + wid;
  while (u < NUNITS){
    // A fragments (fp16 h/m): rows g, g+8; k = 2tg+{0,1,8,9,16,17}
    uint32_t AH[6], AM[6];
    {
      const int n0 = u*16 + g, n1 = n0 + 8;
      const float* p0 = x + (size_t)(n0 >> 12)*(Dd*Ll) + (n0 & (Ll-1));
      const float* p1 = x + (size_t)(n1 >> 12)*(Dd*Ll) + (n1 & (Ll-1));
      #pragma unroll
      for (int j = 0; j < 3; j++){               // k-pair groups: base 2tg + {0,8,16}
        const int ka = 2*tg + j*8, kb = ka + 1;
        float va0 = (ka < Dd) ? __ldg(p0 + ka*Ll) : ((ka == Dd) ? 1.f : 0.f);
        float vb0 = (kb < Dd) ? __ldg(p0 + kb*Ll) : ((kb == Dd) ? 1.f : 0.f);
        float va1 = (ka < Dd) ? __ldg(p1 + ka*Ll) : ((ka == Dd) ? 1.f : 0.f);
        float vb1 = (kb < Dd) ? __ldg(p1 + kb*Ll) : ((kb == Dd) ? 1.f : 0.f);
        __half ha0 = __float2half_rn(va0), hb0 = __float2half_rn(vb0);
        __half ha1 = __float2half_rn(va1), hb1 = __float2half_rn(vb1);
        AH[2*j]   = packh(ha0, hb0);
        AH[2*j+1] = packh(ha1, hb1);
        AM[2*j]   = packh(__float2half_rn(va0 - __half2float(ha0)), __float2half_rn(vb0 - __half2float(hb0)));
        AM[2*j+1] = packh(__float2half_rn(va1 - __half2float(ha1)), __float2half_rn(vb1 - __half2float(hb1)));
      }
    }

    float best0 = -3.4e38f, best1 = -3.4e38f;
    int   idx0 = 0, idx1 = 0;
    const float z[4] = {0.f, 0.f, 0.f, 0.f};

    #pragma unroll 2
    for (int nb = 0; nb < 128; nb++){
      const uint32_t rb = (uint32_t)nb*(8u*ROWW*4u) + lanoff;
      uint32_t bh0, bh1, bh2, bm0, bm1, bm2;
      lds32(bh0, HB + rb); lds32(bh1, HB + rb + 16); lds32(bh2, HB + rb + 32);
      lds32(bm0, MB + rb); lds32(bm1, MB + rb + 16); lds32(bm2, MB + rb + 32);

      // single serial-chained accumulator: no combine FADDs
      float d4[4];
      mma_f16  (d4, AH[0], AH[1], AH[2], AH[3], bh0, bh1, z);   // hh c1
      mma_f16_k8(d4, AH[4], AH[5], bh2, d4);                    // hh c2 (k8)
      mma_f16  (d4, AH[0], AH[1], AH[2], AH[3], bm0, bm1, d4);  // hm c1
      mma_f16_k8(d4, AH[4], AH[5], bm2, d4);                    // hm c2 (k8, incl bias_m)
      mma_f16  (d4, AM[0], AM[1], AM[2], AM[3], bh0, bh1, d4);  // mh c1
      mma_f16_k8(d4, AM[4], AM[5], bh2, d4);                    // mh c2 (k8)

      const int c0 = nb*8 + 2*tg;
      float m0 = fmaxf(d4[0], d4[1]);
      if (m0 > best0){ best0 = m0; idx0 = c0 + ((d4[1] > d4[0]) ? 1 : 0); }
      float m1 = fmaxf(d4[2], d4[3]);
      if (m1 > best1){ best1 = m1; idx1 = c0 + ((d4[3] > d4[2]) ? 1 : 0); }
    }

    // reduce across the 4 lanes sharing each row
    #pragma unroll
    for (int off = 1; off <= 2; off <<= 1){
      float s0 = __shfl_xor_sync(0xFFFFFFFFu, best0, off);
      int   i0 = __shfl_xor_sync(0xFFFFFFFFu, idx0,  off);
      if (s0 > best0 || (s0 == best0 && i0 < idx0)){ best0 = s0; idx0 = i0; }
      float s1 = __shfl_xor_sync(0xFFFFFFFFu, best1, off);
      int   i1 = __shfl_xor_sync(0xFFFFFFFFu, idx1,  off);
      if (s1 > best1 || (s1 == best1 && i1 < idx1)){ best1 = s1; idx1 = i1; }
    }
    // distribute: lane j<16 gets code for point u*16+j
    const int src = (lane & 7)*4;
    const int c0s = __shfl_sync(0xFFFFFFFFu, idx0, src);
    const int c1s = __shfl_sync(0xFFFFFFFFu, idx1, src);

    if (lane < 16){
      const int code = (lane < 8) ? c0s : c1s;
      const int n = u*16 + lane;
      const int bb = n >> 12, l = n & (Ll-1);
      const float* xp = x + (size_t)bb*(Dd*Ll) + l;
      float* op = out + (size_t)bb*(Dd*Ll) + l;

      float mx = -3.4e38f, mq = -3.4e38f;
      #pragma unroll 4
      for (int d = 0; d < Dd; d++){
        float xv = __ldg(xp + d*Ll);
        float qv = __half2float(Hh[code*40 + d]) + __half2float(Hm[code*40 + d]);
        mx = fmaxf(mx, xv); mq = fmaxf(mq, qv);
      }
      float Sx = 0.f, Sq = 0.f, A = 0.f, Cr = 0.f;
      #pragma unroll 4
      for (int d = 0; d < Dd; d++){
        float xv = __ldg(xp + d*Ll);
        float qv = __half2float(Hh[code*40 + d]) + __half2float(Hm[code*40 + d]);
        op[d*Ll] = xv + (qv - xv);
        float xs = xv - mx;
        float ex = __expf(xs), eq = __expf(qv - mq);
        Sx += ex; Sq += eq;
        A  = fmaf(ex, xs, A);
        Cr = fmaf(ex, eq, Cr);
      }
      klacc += A/Sx - __logf(Sx) - Cr/(Sx*Sq);
      atomicAdd(&g_hist[code], 1);
    }

    if (lane == 0) u = NWARPS + atomicAdd(&g_work, 1);
    u = __shfl_sync(0xFFFFFFFFu, u, 0);
  }

  // block-level KL reduction, one atomic per block
  #pragma unroll
  for (int off = 16; off; off >>= 1) klacc += __shfl_xor_sync(0xFFFFFFFFu, klacc, off);
  if (lane == 0) swr[wid] = klacc;
  __syncthreads();
  if (tid == 0){
    float s = 0.f;
    #pragma unroll
    for (int w = 0; w < WPB; w++) s += swr[w];
    atomicAdd(&g_kl, s);
  }

  __threadfence();
  __syncthreads();
  if (tid == 0) slast = (atomicAdd(&g_done, 1) == NBLK - 1);
  __syncthreads();
  if (slast){
    float s = 0.f;
    for (int k = tid; k < Kk; k += NTHR){
      float a = (float)(*(volatile int*)&g_hist[k]) * (1.f/(float)Nn);
      s += a * logf(a + 1e-10f);
      g_hist[k] = 0;
    }
    #pragma unroll
    for (int off = 16; off; off >>= 1) s += __shfl_xor_sync(0xFFFFFFFFu, s, off);
    if (lane == 0) swr[wid] = s;
    __syncthreads();
    if (tid == 0){
      float t = 0.f;
      #pragma unroll
      for (int w = 0; w < WPB; w++) t += swr[w];
      if (out_size >= NDLs + 2){
        out[NDLs]     = 0.1f * ((*(volatile float*)&g_kl) / (float)Bb);
        out[NDLs + 1] = expf(-t);
      }
      g_kl = 0.f; g_done = 0; g_work = 0;
    }
  }
}

extern "C" void kernel_launch(void* const* d_in, const int* in_sizes, int n_in,
                              void* d_out, int out_size){
  const float* x   = (const float*)d_in[0];
  const float* emb = (const float*)d_in[1];
  float* out = (float*)d_out;
  cudaFuncSetAttribute(vq_main, cudaFuncAttributeMaxDynamicSharedMemorySize, SMEM_BYTES);
  vq_main<<<NBLK, NTHR, SMEM_BYTES>>>(x, emb, out, out_size);
}